// round 17
// baseline (speedup 1.0000x reference)
#include <cuda_runtime.h>
#include <cuda_fp16.h>
#include <cstdint>

// Problem constants
#define BATCH   8
#define CIN     384
#define NPIX    3136           // 56*56
#define WWID    56
#define BP      25088          // BATCH*NPIX
#define INNER   512
#define KVOUT   1024
#define HEADS   8
#define DH      64
#define NBH     64
#define SCALE_F 0.125f
#define EPS_F   1e-5f
#define NSPLIT  14

// ---------------------------------------------------------------------------
// Scratch (device globals)
// ---------------------------------------------------------------------------
__device__ __align__(16) __half g_yq_h [(size_t)BP * CIN];   // dwconv out, q path  [n][c]
__device__ __align__(16) __half g_ykv_h[(size_t)BP * CIN];   // dwconv out, kv path [n][c]
__device__ __align__(16) __half g_q_h [(size_t)INNER * BP];  // q   [m][n] fp16
__device__ __align__(16) __half g_kv_h[(size_t)KVOUT * BP];  // k|v [m][n] fp16
__device__ __align__(16) __half g_att_h[(size_t)BP * INNER]; // attention out [n][o]
__device__ __align__(16) __half g_wq_h [INNER * CIN];        // fp16 weights
__device__ __align__(16) __half g_wkv_h[KVOUT * CIN];
__device__ __align__(16) __half g_wo_h [CIN * INNER];
__device__ __align__(16) float g_diag[NBH * NPIX];
__device__ float g_ktvp[NSPLIT * NBH * DH * DH];
__device__ float g_ktv [NBH * DH * DH];
__device__ float g_red[512];
__device__ float g_m0[1];

// ---------------------------------------------------------------------------
// Helpers
// ---------------------------------------------------------------------------
__device__ __forceinline__ uint32_t smem_u32(const void* p) {
    uint32_t a;
    asm("{ .reg .u64 t; cvta.to.shared.u64 t, %1; cvt.u32.u64 %0, t; }" : "=r"(a) : "l"(p));
    return a;
}
__device__ __forceinline__ void cp_async16(uint32_t dst, const void* src) {
    asm volatile("cp.async.cg.shared.global [%0], [%1], 16;" :: "r"(dst), "l"(src));
}
#define CP_COMMIT() asm volatile("cp.async.commit_group;" ::: "memory")
#define CP_WAIT(N)  asm volatile("cp.async.wait_group %0;" :: "n"(N) : "memory")

__device__ __forceinline__ void mma_f16(float* c, const uint32_t* a, const uint32_t* b) {
    asm volatile(
        "mma.sync.aligned.m16n8k16.row.col.f32.f16.f16.f32 "
        "{%0,%1,%2,%3}, {%4,%5,%6,%7}, {%8,%9}, {%0,%1,%2,%3};"
        : "+f"(c[0]), "+f"(c[1]), "+f"(c[2]), "+f"(c[3])
        : "r"(a[0]), "r"(a[1]), "r"(a[2]), "r"(a[3]), "r"(b[0]), "r"(b[1]));
}
__device__ __forceinline__ void ldsm_x4(uint32_t& r0, uint32_t& r1, uint32_t& r2, uint32_t& r3,
                                        uint32_t addr) {
    asm volatile("ldmatrix.sync.aligned.m8n8.x4.shared.b16 {%0,%1,%2,%3}, [%4];"
                 : "=r"(r0), "=r"(r1), "=r"(r2), "=r"(r3) : "r"(addr));
}

#define NW1 (INNER * CIN)
#define NW2 (KVOUT * CIN)
#define NW3 (CIN * INNER)

// ---------------------------------------------------------------------------
// 1) Depthwise 3x3 conv + BN, output TRANSPOSED [n][c] fp16.
//    Each thread computes 4 adjacent pixels x 2 channels.
//    Weight fp32->fp16 conversion folded in (one guarded pass over all blocks).
// ---------------------------------------------------------------------------
__global__ void dwconv_bn_kernel(
    const float* __restrict__ x,
    const float* __restrict__ w1, const float* __restrict__ g1, const float* __restrict__ b1,
    const float* __restrict__ m1, const float* __restrict__ v1,
    const float* __restrict__ w2, const float* __restrict__ g2, const float* __restrict__ b2,
    const float* __restrict__ m2, const float* __restrict__ v2,
    const float* __restrict__ wq_pw, const float* __restrict__ wkv_pw,
    const float* __restrict__ wo)
{
    __shared__ float s1[32][65];
    __shared__ float s2[32][65];
    int b  = blockIdx.z;
    int ct = blockIdx.y;     // 12 channel tiles of 32
    int pt = blockIdx.x;     // 49 pixel tiles of 64
    int tid = threadIdx.x;

    // folded weight conversion (independent of conv work)
    {
        int gid = ((b * 12 + ct) * 49 + pt) * 256 + tid;
        if (gid < NW1) {
            g_wq_h[gid] = __float2half_rn(wq_pw[gid]);
        } else if (gid < NW1 + NW2) {
            g_wkv_h[gid - NW1] = __float2half_rn(wkv_pw[gid - NW1]);
        } else if (gid < NW1 + NW2 + NW3) {
            g_wo_h[gid - NW1 - NW2] = __float2half_rn(wo[gid - NW1 - NW2]);
        }
    }

    int quad  = tid & 15;    // pixel quad 0..15 (4 pixels each)
    int c_sub = tid >> 4;    // 0..15
    int p = pt * 64 + quad * 4;
    int h = p / WWID, w = p % WWID;

#pragma unroll
    for (int i = 0; i < 2; i++) {
        int c_loc = i * 16 + c_sub;
        int c = ct * 32 + c_loc;
        const float* xb = x + ((size_t)(b * CIN + c)) * NPIX;
        const float* wp1 = w1 + c * 9;
        const float* wp2 = w2 + c * 9;
        float a1[4] = {0.f, 0.f, 0.f, 0.f};
        float a2[4] = {0.f, 0.f, 0.f, 0.f};
#pragma unroll
        for (int kh = 0; kh < 3; kh++) {
            int hh = h + kh - 1;
            if (hh < 0 || hh >= WWID) continue;
            const float* row = xb + hh * WWID;
            float xv[6];
            xv[0] = (w > 0) ? row[w - 1] : 0.f;
            float4 mid = *(const float4*)(row + w);
            xv[1] = mid.x; xv[2] = mid.y; xv[3] = mid.z; xv[4] = mid.w;
            xv[5] = (w + 4 < WWID) ? row[w + 4] : 0.f;
            float c10 = wp1[kh * 3 + 0], c11 = wp1[kh * 3 + 1], c12 = wp1[kh * 3 + 2];
            float c20 = wp2[kh * 3 + 0], c21 = wp2[kh * 3 + 1], c22 = wp2[kh * 3 + 2];
#pragma unroll
            for (int j = 0; j < 4; j++) {
                a1[j] += xv[j] * c10 + xv[j+1] * c11 + xv[j+2] * c12;
                a2[j] += xv[j] * c20 + xv[j+1] * c21 + xv[j+2] * c22;
            }
        }
        float inv1 = g1[c] * rsqrtf(v1[c] + EPS_F);
        float inv2 = g2[c] * rsqrtf(v2[c] + EPS_F);
        float ad1 = b1[c] - m1[c] * inv1;
        float ad2 = b2[c] - m2[c] * inv2;
#pragma unroll
        for (int j = 0; j < 4; j++) {
            s1[c_loc][quad * 4 + j] = a1[j] * inv1 + ad1;
            s2[c_loc][quad * 4 + j] = a2[j] * inv2 + ad2;
        }
    }
    __syncthreads();

#pragma unroll
    for (int i = 0; i < 2; i++) {
        int idx = tid + i * 256;
        int pp  = idx >> 3;
        int cq  = idx & 7;
        size_t base = ((size_t)(b * NPIX + pt * 64 + pp)) * CIN + ct * 32 + cq * 4;
        __half2 q0 = __floats2half2_rn(s1[cq*4+0][pp], s1[cq*4+1][pp]);
        __half2 q1 = __floats2half2_rn(s1[cq*4+2][pp], s1[cq*4+3][pp]);
        __half2 k0 = __floats2half2_rn(s2[cq*4+0][pp], s2[cq*4+1][pp]);
        __half2 k1 = __floats2half2_rn(s2[cq*4+2][pp], s2[cq*4+3][pp]);
        *(__half2*)(g_yq_h  + base)     = q0;
        *(__half2*)(g_yq_h  + base + 2) = q1;
        *(__half2*)(g_ykv_h + base)     = k0;
        *(__half2*)(g_ykv_h + base + 2) = k1;
    }
}

// ---------------------------------------------------------------------------
// 2) fp16 mma.sync GEMM body, 3-stage cp.async pipeline, ldmatrix fragments.
//    K-tile 64 halves. C[m][n] = sum_k A[m][k] * B[n][k], fp32 accum.
// ---------------------------------------------------------------------------
#define KTILE   64
#define SROW_H  72
#define TILE_H  (128 * SROW_H)
#define NSTAGE  3
#define STAGE_BYTES (2 * TILE_H * 2)
#define SMEM_GEMM_BYTES (NSTAGE * STAGE_BYTES)

template<int MODE>
__device__ __forceinline__ void gemm_body(
    __half* smem, const __half* __restrict__ A, const __half* __restrict__ Bm,
    void* __restrict__ Cv, int Kd, const float* __restrict__ bias, int m0, int n0)
{
    int tid = threadIdx.x;
    int wid = tid >> 5;
    int lane = tid & 31;
    int grp = lane >> 2;
    int qid = lane & 3;
    int warp_m = wid & 1;
    int warp_n = wid >> 1;
    int KT = Kd / KTILE;

    uint32_t smem_b = smem_u32(smem);

    auto load_tile = [&](int kt, int stage) {
        int k0 = kt * KTILE;
        uint32_t dA = smem_b + (uint32_t)stage * STAGE_BYTES;
        uint32_t dB = dA + TILE_H * 2;
#pragma unroll
        for (int i = 0; i < 4; i++) {
            int idx = tid + i * 256;
            int row = idx >> 3, q = idx & 7;
            cp_async16(dA + (uint32_t)(row * SROW_H + q * 8) * 2,
                       A + (size_t)(m0 + row) * Kd + k0 + q * 8);
        }
#pragma unroll
        for (int i = 0; i < 4; i++) {
            int idx = tid + i * 256;
            int row = idx >> 3, q = idx & 7;
            cp_async16(dB + (uint32_t)(row * SROW_H + q * 8) * 2,
                       Bm + (size_t)(n0 + row) * Kd + k0 + q * 8);
        }
    };

    float acc[4][4][4];
#pragma unroll
    for (int mt = 0; mt < 4; mt++)
#pragma unroll
        for (int nt = 0; nt < 4; nt++)
#pragma unroll
            for (int r = 0; r < 4; r++) acc[mt][nt][r] = 0.f;

    load_tile(0, 0);
    CP_COMMIT();
    load_tile(1, 1);
    CP_COMMIT();

    int rsel = (lane & 7) + ((lane >> 3) & 1) * 8;
    int csel = (lane >> 4) * 8;

    int stage = 0;
    for (int kt = 0; kt < KT; kt++) {
        CP_WAIT(1);
        __syncthreads();

        uint32_t As_u = smem_b + (uint32_t)stage * STAGE_BYTES;
        uint32_t Bs_u = As_u + TILE_H * 2;

#pragma unroll
        for (int ks = 0; ks < 4; ks++) {
            int col = ks * 16 + csel;
            uint32_t afr[4][4], bfr[4][2];
#pragma unroll
            for (int mt = 0; mt < 4; mt++) {
                uint32_t addr = As_u +
                    (uint32_t)((warp_m * 64 + mt * 16 + rsel) * SROW_H + col) * 2;
                ldsm_x4(afr[mt][0], afr[mt][1], afr[mt][2], afr[mt][3], addr);
            }
#pragma unroll
            for (int p = 0; p < 2; p++) {
                uint32_t addr = Bs_u +
                    (uint32_t)((warp_n * 32 + p * 16 + rsel) * SROW_H + col) * 2;
                uint32_t b0, b1, b2, b3;
                ldsm_x4(b0, b1, b2, b3, addr);
                bfr[p*2  ][0] = b0; bfr[p*2+1][0] = b1;
                bfr[p*2  ][1] = b2; bfr[p*2+1][1] = b3;
            }
#pragma unroll
            for (int mt = 0; mt < 4; mt++)
#pragma unroll
                for (int nt = 0; nt < 4; nt++)
                    mma_f16(acc[mt][nt], afr[mt], bfr[nt]);
        }

        if (kt + 2 < KT) {
            int nstage = stage + 2; if (nstage >= NSTAGE) nstage -= NSTAGE;
            load_tile(kt + 2, nstage);
        }
        CP_COMMIT();
        stage = (stage + 1 == NSTAGE) ? 0 : stage + 1;
    }

    // Epilogue
#pragma unroll
    for (int mt = 0; mt < 4; mt++) {
        int r0 = m0 + warp_m * 64 + mt * 16 + grp;
        int r1 = r0 + 8;
        float bs0 = (MODE == 1) ? bias[r0] : 0.f;
        float bs1 = (MODE == 1) ? bias[r1] : 0.f;
#pragma unroll
        for (int nt = 0; nt < 4; nt++) {
            int n = n0 + warp_n * 32 + nt * 8 + qid * 2;
            float* a4 = acc[mt][nt];
            if (MODE == 0) {
                __half* Ch = (__half*)Cv;
                *(__half2*)(Ch + (size_t)r0 * BP + n) = __floats2half2_rn(a4[0], a4[1]);
                *(__half2*)(Ch + (size_t)r1 * BP + n) = __floats2half2_rn(a4[2], a4[3]);
            } else {
                float* C = (float*)Cv;
                int bb = n / NPIX, p = n - bb * NPIX;
                *(float2*)(C + ((size_t)bb * CIN + r0) * NPIX + p) =
                    make_float2(a4[0] + bs0, a4[1] + bs0);
                *(float2*)(C + ((size_t)bb * CIN + r1) * NPIX + p) =
                    make_float2(a4[2] + bs1, a4[3] + bs1);
            }
        }
    }
}

// Merged q + kv projection: pointer-select, then ONE gemm_body call site.
__global__ void __launch_bounds__(256, 2) gemm_qkv()
{
    extern __shared__ __half smem[];
    int y = blockIdx.y;
    const __half* A;
    const __half* Bm;
    __half* C;
    int m0;
    if (y < 4) { A = g_wq_h;  Bm = g_yq_h;  C = g_q_h;  m0 = y * 128; }
    else       { A = g_wkv_h; Bm = g_ykv_h; C = g_kv_h; m0 = (y - 4) * 128; }
    gemm_body<0>(smem, A, Bm, C, CIN, nullptr, m0, blockIdx.x * 128);
}

// Output projection GEMM (+bias, NCHW scatter)
__global__ void __launch_bounds__(256, 2) gemm_out(float* __restrict__ C,
                                                   const float* __restrict__ bias)
{
    extern __shared__ __half smem[];
    gemm_body<1>(smem, g_wo_h, g_att_h, C, INNER, bias, blockIdx.y * 128, blockIdx.x * 128);
}

// ---------------------------------------------------------------------------
// 3) diag (4 pixels per thread, 8B loads) + fused block partial sum
// ---------------------------------------------------------------------------
__global__ void diag_kernel()
{
    __shared__ float sm[256];
    int tid = threadIdx.x;
    int idx = blockIdx.x * 256 + tid;                  // over NBH * NPIX/4 = 50176
    int n4  = idx % (NPIX / 4);
    int bh  = idx / (NPIX / 4);
    int b = bh >> 3, h = bh & 7;
    int n = n4 * 4;
    size_t base = (size_t)b * NPIX + n;
    float s0 = 0.f, s1 = 0.f, s2 = 0.f, s3 = 0.f;
#pragma unroll 8
    for (int d = 0; d < DH; d++) {
        uint2 qu = *(const uint2*)(g_q_h  + (size_t)(h * DH + d) * BP + base);
        uint2 ku = *(const uint2*)(g_kv_h + (size_t)(h * DH + d) * BP + base);
        float2 qa = __half22float2(*reinterpret_cast<__half2*>(&qu.x));
        float2 qb = __half22float2(*reinterpret_cast<__half2*>(&qu.y));
        float2 ka = __half22float2(*reinterpret_cast<__half2*>(&ku.x));
        float2 kb = __half22float2(*reinterpret_cast<__half2*>(&ku.y));
        s0 += qa.x * ka.x;  s1 += qa.y * ka.y;
        s2 += qb.x * kb.x;  s3 += qb.y * kb.y;
    }
    s0 *= SCALE_F; s1 *= SCALE_F; s2 *= SCALE_F; s3 *= SCALE_F;
    *(float4*)(g_diag + bh * NPIX + n) = make_float4(s0, s1, s2, s3);

    sm[tid] = s0 + s1 + s2 + s3;
    __syncthreads();
    for (int st = 128; st > 0; st >>= 1) {
        if (tid < st) sm[tid] += sm[tid + st];
        __syncthreads();
    }
    if (tid == 0) g_red[blockIdx.x] = sm[0];
}

// reduce 196 block partials -> m0
__global__ void reduce_diag2()
{
    __shared__ float sm[256];
    int tid = threadIdx.x;
    sm[tid] = (tid < 196) ? g_red[tid] : 0.f;
    __syncthreads();
    for (int st = 128; st > 0; st >>= 1) {
        if (tid < st) sm[tid] += sm[tid + st];
        __syncthreads();
    }
    if (tid == 0) g_m0[0] = sm[0];
}

// ---------------------------------------------------------------------------
// 4) ktv partials on tensor cores (grid NSPLIT x 64), fp32 accum
// ---------------------------------------------------------------------------
#define KTV_SROW 40
#define KTV_OP_H (64 * KTV_SROW)

__global__ void __launch_bounds__(128) ktv_partial()
{
    __shared__ __half sK[2 * KTV_OP_H];
    __shared__ __half sV[2 * KTV_OP_H];

    int split = blockIdx.x;
    int bh = blockIdx.y;
    int b = bh >> 3, h = bh & 7;
    int tid = threadIdx.x;
    int wid = tid >> 5;
    int lane = tid & 31;
    int grp = lane >> 2;
    int qid = lane & 3;

    uint32_t sK_u = smem_u32(sK);
    uint32_t sV_u = smem_u32(sV);

    size_t base = (size_t)b * NPIX + split * (NPIX / NSPLIT);
    const __half* Kg = g_kv_h + (size_t)(h * DH) * BP + base;
    const __half* Vg = g_kv_h + (size_t)(INNER + h * DH) * BP + base;

    auto load_chunk = [&](int kt, int s) {
        int n0 = kt * 32;
        uint32_t dK = sK_u + (uint32_t)s * (KTV_OP_H * 2);
        uint32_t dV = sV_u + (uint32_t)s * (KTV_OP_H * 2);
#pragma unroll
        for (int i = 0; i < 2; i++) {
            int idx = tid + i * 128;
            int row = idx >> 2, q = idx & 3;
            cp_async16(dK + (uint32_t)(row * KTV_SROW + q * 8) * 2,
                       Kg + (size_t)row * BP + n0 + q * 8);
        }
#pragma unroll
        for (int i = 0; i < 2; i++) {
            int idx = tid + i * 128;
            int row = idx >> 2, q = idx & 3;
            cp_async16(dV + (uint32_t)(row * KTV_SROW + q * 8) * 2,
                       Vg + (size_t)row * BP + n0 + q * 8);
        }
    };

    float acc[8][4];
#pragma unroll
    for (int nt = 0; nt < 8; nt++)
#pragma unroll
        for (int r = 0; r < 4; r++) acc[nt][r] = 0.f;

    const int KT = (NPIX / NSPLIT) / 32;   // 7
    load_chunk(0, 0);
    CP_COMMIT();

    int rsel = (lane & 7) + ((lane >> 3) & 1) * 8;
    int csel = (lane >> 4) * 8;

    for (int kt = 0; kt < KT; kt++) {
        int buf = kt & 1;
        if (kt + 1 < KT) {
            load_chunk(kt + 1, buf ^ 1);
            CP_COMMIT();
            CP_WAIT(1);
        } else {
            CP_WAIT(0);
        }
        __syncthreads();

        uint32_t Kb = sK_u + (uint32_t)buf * (KTV_OP_H * 2);
        uint32_t Vb = sV_u + (uint32_t)buf * (KTV_OP_H * 2);

#pragma unroll
        for (int ks = 0; ks < 2; ks++) {
            int col = ks * 16 + csel;
            uint32_t afr[4];
            ldsm_x4(afr[0], afr[1], afr[2], afr[3],
                    Kb + (uint32_t)((wid * 16 + rsel) * KTV_SROW + col) * 2);
            uint32_t bfr[8][2];
#pragma unroll
            for (int p = 0; p < 4; p++) {
                uint32_t b0, b1, b2, b3;
                ldsm_x4(b0, b1, b2, b3,
                        Vb + (uint32_t)((p * 16 + rsel) * KTV_SROW + col) * 2);
                bfr[p*2  ][0] = b0; bfr[p*2+1][0] = b1;
                bfr[p*2  ][1] = b2; bfr[p*2+1][1] = b3;
            }
#pragma unroll
            for (int nt = 0; nt < 8; nt++)
                mma_f16(acc[nt], afr, bfr[nt]);
        }
        __syncthreads();
    }

    float* dst = g_ktvp + ((size_t)(split * NBH + bh)) * (DH * DH);
    int d0 = wid * 16 + grp;
    int d1 = d0 + 8;
#pragma unroll
    for (int nt = 0; nt < 8; nt++) {
        int e = nt * 8 + qid * 2;
        *(float2*)(dst + d0 * DH + e) = make_float2(acc[nt][0], acc[nt][1]);
        *(float2*)(dst + d1 * DH + e) = make_float2(acc[nt][2], acc[nt][3]);
    }
}

__global__ void ktv_reduce()
{
    int idx = blockIdx.x * blockDim.x + threadIdx.x;
    if (idx >= NBH * DH * DH) return;
    float s = 0.f;
#pragma unroll
    for (int sp = 0; sp < NSPLIT; sp++)
        s += g_ktvp[(size_t)sp * (NBH * DH * DH) + idx];
    g_ktv[idx] = s;
}

// ---------------------------------------------------------------------------
// 5) att_out: 128 pixels per block (2 pixel-pairs per thread), guard on NPIX.
// ---------------------------------------------------------------------------
__global__ void att_out_kernel()
{
    __shared__ float ktv_s[DH * DH];
    int bh = blockIdx.y;
    int b = bh >> 3, h = bh & 7;

    for (int i = threadIdx.x; i < DH * DH; i += 256)
        ktv_s[i] = g_ktv[bh * (DH * DH) + i];
    __syncthreads();

    float m0 = g_m0[0];
    int pn = threadIdx.x & 31;
    int eg = threadIdx.x >> 5;

#pragma unroll
    for (int half = 0; half < 2; half++) {
        int n = blockIdx.x * 128 + half * 64 + pn * 2;
        if (n >= NPIX) break;
        size_t base = (size_t)b * NPIX + n;

        float acc0[8], acc1[8];
#pragma unroll
        for (int j = 0; j < 8; j++) { acc0[j] = 0.f; acc1[j] = 0.f; }

#pragma unroll 4
        for (int d = 0; d < DH; d++) {
            float2 qf = __half22float2(*(const __half2*)(g_q_h + (size_t)(h * DH + d) * BP + base));
            const float* kv = ktv_s + d * DH + eg * 8;
#pragma unroll
            for (int j = 0; j < 8; j++) {
                acc0[j] += qf.x * kv[j];
                acc1[j] += qf.y * kv[j];
            }
        }

        float c0 = m0 - g_diag[bh * NPIX + n];
        float c1 = m0 - g_diag[bh * NPIX + n + 1];
        __half out0[8], out1[8];
#pragma unroll
        for (int j = 0; j < 8; j++) {
            int e = eg * 8 + j;
            float2 vf = __half22float2(*(const __half2*)(g_kv_h + (size_t)(INNER + h * DH + e) * BP + base));
            out0[j] = __float2half_rn(SCALE_F * acc0[j] + c0 * vf.x);
            out1[j] = __float2half_rn(SCALE_F * acc1[j] + c1 * vf.y);
        }
        __half2* d0 = (__half2*)(g_att_h + base * INNER + h * DH + eg * 8);
        __half2* d1 = (__half2*)(g_att_h + (base + 1) * INNER + h * DH + eg * 8);
#pragma unroll
        for (int j = 0; j < 4; j++) {
            d0[j] = __halves2half2(out0[j*2], out0[j*2+1]);
            d1[j] = __halves2half2(out1[j*2], out1[j*2+1]);
        }
    }
}

// ---------------------------------------------------------------------------
// Launch
// ---------------------------------------------------------------------------
extern "C" void kernel_launch(void* const* d_in, const int* in_sizes, int n_in,
                              void* d_out, int out_size)
{
    const float* x       = (const float*)d_in[0];
    const float* wq_dw   = (const float*)d_in[1];
    const float* wq_g    = (const float*)d_in[2];
    const float* wq_b    = (const float*)d_in[3];
    const float* wq_m    = (const float*)d_in[4];
    const float* wq_v    = (const float*)d_in[5];
    const float* wq_pw   = (const float*)d_in[6];
    const float* wkv_dw  = (const float*)d_in[7];
    const float* wkv_g   = (const float*)d_in[8];
    const float* wkv_b   = (const float*)d_in[9];
    const float* wkv_m   = (const float*)d_in[10];
    const float* wkv_v   = (const float*)d_in[11];
    const float* wkv_pw  = (const float*)d_in[12];
    const float* wo      = (const float*)d_in[13];
    const float* bo      = (const float*)d_in[14];
    float* out = (float*)d_out;

    cudaFuncSetAttribute(gemm_qkv, cudaFuncAttributeMaxDynamicSharedMemorySize, SMEM_GEMM_BYTES);
    cudaFuncSetAttribute(gemm_out, cudaFuncAttributeMaxDynamicSharedMemorySize, SMEM_GEMM_BYTES);

    // 1) depthwise conv + BN + folded weight conversion
    dwconv_bn_kernel<<<dim3(49, 12, 8), 256>>>(
        x, wq_dw, wq_g, wq_b, wq_m, wq_v,
           wkv_dw, wkv_g, wkv_b, wkv_m, wkv_v,
           wq_pw, wkv_pw, wo);

    // 2) q + kv projections, single tensor-core launch (K-tile 64)
    gemm_qkv<<<dim3(196, 12), 256, SMEM_GEMM_BYTES>>>();

    // 3) attention middle
    diag_kernel<<<(NBH * NPIX / 4) / 256, 256>>>();
    reduce_diag2<<<1, 256>>>();
    ktv_partial<<<dim3(NSPLIT, NBH), 128>>>();
    ktv_reduce<<<(NBH * DH * DH) / 256, 256>>>();
    att_out_kernel<<<dim3((NPIX + 127) / 128, NBH), 256>>>();

    // 4) output projection (+bias, NCHW scatter)
    gemm_out<<<dim3(196, 3), 256, SMEM_GEMM_BYTES>>>(out, bo);
}